// round 14
// baseline (speedup 1.0000x reference)
#include <cuda_runtime.h>

#define B_    2048
#define FS_   32
#define FA_   16
#define T_    512
#define H_    64
#define SQRT_DT_ 0.22360679774997896f
#define MIN_V_  (-5.0f)
#define MAX_V_  (5.0f)

typedef unsigned long long u64;

__device__ __forceinline__ u64 pack2(float lo, float hi) {
    u64 r; asm("mov.b64 %0, {%1, %2};" : "=l"(r) : "f"(lo), "f"(hi)); return r;
}
__device__ __forceinline__ float2 unpack2(u64 v) {
    float2 f; asm("mov.b64 {%0, %1}, %2;" : "=f"(f.x), "=f"(f.y) : "l"(v)); return f;
}
__device__ __forceinline__ u64 ffma2(u64 a, u64 b, u64 c) {
    u64 d; asm("fma.rn.f32x2 %0, %1, %2, %3;" : "=l"(d) : "l"(a), "l"(b), "l"(c)); return d;
}
__device__ __forceinline__ u64 fadd2(u64 a, u64 b) {
    u64 d; asm("add.rn.f32x2 %0, %1, %2;" : "=l"(d) : "l"(a), "l"(b)); return d;
}
// accurate tanh from ex2.approx + rcp.approx (~1e-7 abs err)
__device__ __forceinline__ float tanh_acc(float x) {
    float e, r;
    asm("ex2.approx.f32 %0, %1;" : "=f"(e) : "f"(x * 2.8853900817779268f));
    asm("rcp.approx.f32 %0, %1;" : "=f"(r) : "f"(e + 1.0f));
    return (e - 1.0f) * r;
}

// R10 topology (256 thr = 4 (f,g) pairs x 4 elements, grid=128, full register
// weights, ONE named barrier/step, redundant finalize, batched STG.64) with
// EXPLICIT software pipelining: named operand buffer sets so loads of group
// q+2 (L1) / q+3 (L2) are issued, in source order, right after the FMAs of
// group q -- giving every LDS 32-64 cycles of cover that ptxas could not
// create on its own at 255 registers.
__global__ void __launch_bounds__(256, 1)
sde_kernel(const float* __restrict__ a_in,   // (B, FA, T)
           const float* __restrict__ x0,     // (B, FS)
           const float* __restrict__ noise,  // (T-1, B, FS)
           const float* __restrict__ Wf1, const float* __restrict__ bf1,
           const float* __restrict__ Wf2, const float* __restrict__ bf2,
           const float* __restrict__ Wg1, const float* __restrict__ bg1,
           const float* __restrict__ Wg2, const float* __restrict__ bg2,
           float* __restrict__ out)          // (B, FS, T)
{
    const int tid  = threadIdx.x;
    const int wid  = tid >> 5;
    const int lane = tid & 31;
    const int pair = wid >> 1;
    const bool is_g = (wid & 1) != 0;
    const int el0  = pair * 4;
    const int gb0  = blockIdx.x * 16 + el0;

    __shared__ __align__(16) float v_sm[8][4][64];        // per-warp x/h buffer
    __shared__ __align__(16) float a_sg[2][16][4][16];    // a tiles, 4 steps, transposed
    __shared__ __align__(16) float ex_sm[2][4][2][4][32]; // {o_f,d} exchange, dbl-buf

    const float* W1 = is_g ? Wg1 : Wf1;
    const float* b1 = is_g ? bg1 : bf1;
    const float* W2 = is_g ? Wg2 : Wf2;
    const float* b2 = is_g ? bg2 : bf2;

    u64 w1a[24], w1b[24], w2p[32];
#pragma unroll
    for (int kp = 0; kp < 24; kp++) {
        w1a[kp] = pack2(W1[(2*kp)*H_ + lane],      W1[(2*kp+1)*H_ + lane]);
        w1b[kp] = pack2(W1[(2*kp)*H_ + lane + 32], W1[(2*kp+1)*H_ + lane + 32]);
    }
#pragma unroll
    for (int kp = 0; kp < 32; kp++) {
        w2p[kp] = pack2(W2[(2*kp)*FS_ + lane], W2[(2*kp+1)*FS_ + lane]);
    }
    const float bias1a = b1[lane];
    const float bias1b = b1[lane + 32];
    const float bias2  = b2[lane];

    const float* a_base  = a_in  + (size_t)gb0 * (FA_*T_) + (size_t)(lane >> 1) * T_ + (lane & 1) * 2;
    const float* nz_base = noise + (size_t)gb0 * FS_ + lane;
    float*       out_b   = out   + (size_t)gb0 * (FS_*T_) + (size_t)lane * T_;

    float2 areg[4];
    float  eps_n[4];
    float2 hist[4];

#pragma unroll
    for (int e = 0; e < 4; e++) {
        float xv = x0[(size_t)(gb0 + e) * FS_ + lane];
        v_sm[wid][e][lane] = xv;
        if (!is_g) hist[e].x = xv;
    }
    if (is_g) {
#pragma unroll
        for (int e = 0; e < 4; e++) {
            float2 v = *reinterpret_cast<const float2*>(a_base + (size_t)e * (FA_*T_));
            a_sg[0][el0 + e][(lane & 1)*2 + 0][lane >> 1] = v.x;
            a_sg[0][el0 + e][(lane & 1)*2 + 1][lane >> 1] = v.y;
        }
#pragma unroll
        for (int e = 0; e < 4; e++)
            areg[e] = *reinterpret_cast<const float2*>(a_base + (size_t)e * (FA_*T_) + 4);
#pragma unroll
        for (int e = 0; e < 4; e++) eps_n[e] = nz_base[e * FS_];
    }
    __syncthreads();

    const int bar_id = 1 + pair;

// ---------------- pipelined-load macros (explicit register args) ----------------
// L1 group q (0..11): q<4 reads a_sg, else v_sm(x). 4 independent LDS.128.
#define L1_LOAD(R0, R1, R2, R3, q_) do { \
    R0 = *((q_) < 4 ? (const ulonglong2*)&a_sg[buf][el0+0][sl][4*(q_)] \
                    : (const ulonglong2*)&v_sm[wid][0][4*((q_)-4)]); \
    R1 = *((q_) < 4 ? (const ulonglong2*)&a_sg[buf][el0+1][sl][4*(q_)] \
                    : (const ulonglong2*)&v_sm[wid][1][4*((q_)-4)]); \
    R2 = *((q_) < 4 ? (const ulonglong2*)&a_sg[buf][el0+2][sl][4*(q_)] \
                    : (const ulonglong2*)&v_sm[wid][2][4*((q_)-4)]); \
    R3 = *((q_) < 4 ? (const ulonglong2*)&a_sg[buf][el0+3][sl][4*(q_)] \
                    : (const ulonglong2*)&v_sm[wid][3][4*((q_)-4)]); \
} while (0)

#define L1_FMA(R0, R1, R2, R3, q_) do { \
    const u64 wA0 = w1a[2*(q_)], wA1 = w1a[2*(q_)+1]; \
    const u64 wB0 = w1b[2*(q_)], wB1 = w1b[2*(q_)+1]; \
    aa[0]=ffma2(R0.x,wA0,aa[0]); aa[1]=ffma2(R1.x,wA0,aa[1]); \
    aa[2]=ffma2(R2.x,wA0,aa[2]); aa[3]=ffma2(R3.x,wA0,aa[3]); \
    ab[0]=ffma2(R0.x,wB0,ab[0]); ab[1]=ffma2(R1.x,wB0,ab[1]); \
    ab[2]=ffma2(R2.x,wB0,ab[2]); ab[3]=ffma2(R3.x,wB0,ab[3]); \
    aa[0]=ffma2(R0.y,wA1,aa[0]); aa[1]=ffma2(R1.y,wA1,aa[1]); \
    aa[2]=ffma2(R2.y,wA1,aa[2]); aa[3]=ffma2(R3.y,wA1,aa[3]); \
    ab[0]=ffma2(R0.y,wB1,ab[0]); ab[1]=ffma2(R1.y,wB1,ab[1]); \
    ab[2]=ffma2(R2.y,wB1,ab[2]); ab[3]=ffma2(R3.y,wB1,ab[3]); \
} while (0)

// L2 group q (0..15): reads h from v_sm. 4 LDS.128, 8 ffma2.
#define L2_LOAD(R0, R1, R2, R3, q_) do { \
    R0 = *(const ulonglong2*)&v_sm[wid][0][4*(q_)]; \
    R1 = *(const ulonglong2*)&v_sm[wid][1][4*(q_)]; \
    R2 = *(const ulonglong2*)&v_sm[wid][2][4*(q_)]; \
    R3 = *(const ulonglong2*)&v_sm[wid][3][4*(q_)]; \
} while (0)

#define L2_FMA(R0, R1, R2, R3, q_) do { \
    const u64 w0 = w2p[2*(q_)], w1x = w2p[2*(q_)+1]; \
    c0[0]=ffma2(R0.x,w0,c0[0]); c0[1]=ffma2(R1.x,w0,c0[1]); \
    c0[2]=ffma2(R2.x,w0,c0[2]); c0[3]=ffma2(R3.x,w0,c0[3]); \
    c1[0]=ffma2(R0.y,w1x,c1[0]); c1[1]=ffma2(R1.y,w1x,c1[1]); \
    c1[2]=ffma2(R2.y,w1x,c1[2]); c1[3]=ffma2(R3.y,w1x,c1[3]); \
} while (0)

#pragma unroll 1
    for (int t = 1; t < T_; t++) {
        const int ai  = t - 1;
        const int tb  = t & 1;
        const int g4  = ai >> 2;
        const int buf = g4 & 1;
        const int sl  = ai & 3;

        float es[4];
        if (is_g) {
#pragma unroll
            for (int e = 0; e < 4; e++) es[e] = eps_n[e] * SQRT_DT_;
            if (t < T_ - 1) {
                const float* np = nz_base + (size_t)t * (B_ * FS_);
#pragma unroll
                for (int e = 0; e < 4; e++) eps_n[e] = np[e * FS_];
            }
        }

        // ---------------- layer 1: 12 groups, 2-deep pipeline ----------------
        u64 aa[4] = {0,0,0,0}, ab[4] = {0,0,0,0};
        {
            ulonglong2 A0, A1, A2, A3, B0, B1, B2, B3;
            L1_LOAD(A0,A1,A2,A3, 0);   L1_LOAD(B0,B1,B2,B3, 1);
            L1_FMA (A0,A1,A2,A3, 0);   L1_LOAD(A0,A1,A2,A3, 2);
            L1_FMA (B0,B1,B2,B3, 1);   L1_LOAD(B0,B1,B2,B3, 3);
            L1_FMA (A0,A1,A2,A3, 2);   L1_LOAD(A0,A1,A2,A3, 4);
            L1_FMA (B0,B1,B2,B3, 3);   L1_LOAD(B0,B1,B2,B3, 5);
            L1_FMA (A0,A1,A2,A3, 4);   L1_LOAD(A0,A1,A2,A3, 6);
            L1_FMA (B0,B1,B2,B3, 5);   L1_LOAD(B0,B1,B2,B3, 7);
            L1_FMA (A0,A1,A2,A3, 6);   L1_LOAD(A0,A1,A2,A3, 8);
            L1_FMA (B0,B1,B2,B3, 7);   L1_LOAD(B0,B1,B2,B3, 9);
            L1_FMA (A0,A1,A2,A3, 8);   L1_LOAD(A0,A1,A2,A3, 10);
            L1_FMA (B0,B1,B2,B3, 9);   L1_LOAD(B0,B1,B2,B3, 11);
            L1_FMA (A0,A1,A2,A3, 10);
            L1_FMA (B0,B1,B2,B3, 11);
        }
        // tanh + stash h (overwrites x in private buffer)
#pragma unroll
        for (int e = 0; e < 4; e++) {
            float2 u = unpack2(aa[e]);
            float2 v = unpack2(ab[e]);
            v_sm[wid][e][lane]      = tanh_acc(u.x + u.y + bias1a);
            v_sm[wid][e][lane + 32] = tanh_acc(v.x + v.y + bias1b);
        }
        __syncwarp();

        // ---------------- layer 2: 16 groups, 3-deep pipeline ----------------
        u64 c0[4] = {0,0,0,0}, c1[4] = {0,0,0,0};
        {
            ulonglong2 A0, A1, A2, A3, B0, B1, B2, B3, C0v, C1v, C2v, C3v;
            L2_LOAD(A0,A1,A2,A3, 0);   L2_LOAD(B0,B1,B2,B3, 1);   L2_LOAD(C0v,C1v,C2v,C3v, 2);
            L2_FMA (A0,A1,A2,A3, 0);   L2_LOAD(A0,A1,A2,A3, 3);
            L2_FMA (B0,B1,B2,B3, 1);   L2_LOAD(B0,B1,B2,B3, 4);
            L2_FMA (C0v,C1v,C2v,C3v, 2); L2_LOAD(C0v,C1v,C2v,C3v, 5);
            L2_FMA (A0,A1,A2,A3, 3);   L2_LOAD(A0,A1,A2,A3, 6);
            L2_FMA (B0,B1,B2,B3, 4);   L2_LOAD(B0,B1,B2,B3, 7);
            L2_FMA (C0v,C1v,C2v,C3v, 5); L2_LOAD(C0v,C1v,C2v,C3v, 8);
            L2_FMA (A0,A1,A2,A3, 6);   L2_LOAD(A0,A1,A2,A3, 9);
            L2_FMA (B0,B1,B2,B3, 7);   L2_LOAD(B0,B1,B2,B3, 10);
            L2_FMA (C0v,C1v,C2v,C3v, 8); L2_LOAD(C0v,C1v,C2v,C3v, 11);
            L2_FMA (A0,A1,A2,A3, 9);   L2_LOAD(A0,A1,A2,A3, 12);
            L2_FMA (B0,B1,B2,B3, 10);  L2_LOAD(B0,B1,B2,B3, 13);
            L2_FMA (C0v,C1v,C2v,C3v, 11); L2_LOAD(C0v,C1v,C2v,C3v, 14);
            L2_FMA (A0,A1,A2,A3, 12);  L2_LOAD(A0,A1,A2,A3, 15);
            L2_FMA (B0,B1,B2,B3, 13);
            L2_FMA (C0v,C1v,C2v,C3v, 14);
            L2_FMA (A0,A1,A2,A3, 15);
        }
        float o[4];
#pragma unroll
        for (int e = 0; e < 4; e++) {
            float2 u = unpack2(fadd2(c0[e], c1[e]));
            o[e] = (u.x + u.y) + bias2;
        }

        // publish
        if (!is_g) {
#pragma unroll
            for (int e = 0; e < 4; e++) ex_sm[tb][pair][0][e][lane] = o[e];
        } else {
#pragma unroll
            for (int e = 0; e < 4; e++) ex_sm[tb][pair][1][e][lane] = o[e] * es[e];
        }

        // g: a-tile staging pre-barrier
        if (is_g) {
            if (sl == 2 && g4 + 1 < 128) {
#pragma unroll
                for (int e = 0; e < 4; e++) {
                    a_sg[buf ^ 1][el0 + e][(lane & 1)*2 + 0][lane >> 1] = areg[e].x;
                    a_sg[buf ^ 1][el0 + e][(lane & 1)*2 + 1][lane >> 1] = areg[e].y;
                }
            }
            if (sl == 3 && g4 + 2 < 128) {
                const float* ap = a_base + (size_t)(g4 + 2) * 4;
#pragma unroll
                for (int e = 0; e < 4; e++)
                    areg[e] = *reinterpret_cast<const float2*>(ap + (size_t)e * (FA_*T_));
            }
        }

        asm volatile("bar.sync %0, 64;" :: "r"(bar_id) : "memory");

        // redundant finalize; f batches output stores into STG.64
#pragma unroll
        for (int e = 0; e < 4; e++) {
            float xv = ex_sm[tb][pair][0][e][lane] + ex_sm[tb][pair][1][e][lane];
            xv = fminf(fmaxf(xv, MIN_V_), MAX_V_);
            v_sm[wid][e][lane] = xv;
            if (!is_g) {
                if (tb) {
                    hist[e].y = xv;
                    *reinterpret_cast<float2*>(out_b + (size_t)e * (FS_*T_) + (t - 1)) = hist[e];
                } else {
                    hist[e].x = xv;
                }
            }
        }
        __syncwarp();
    }

#undef L1_LOAD
#undef L1_FMA
#undef L2_LOAD
#undef L2_FMA
}

extern "C" void kernel_launch(void* const* d_in, const int* in_sizes, int n_in,
                              void* d_out, int out_size) {
    (void)in_sizes; (void)n_in; (void)out_size;
    // metadata order: ts, in_signal, x0, noise, Wf1, bf1, Wf2, bf2, Wg1, bg1, Wg2, bg2
    const float* a_in  = (const float*)d_in[1];
    const float* x0    = (const float*)d_in[2];
    const float* noise = (const float*)d_in[3];
    const float* Wf1   = (const float*)d_in[4];
    const float* bf1   = (const float*)d_in[5];
    const float* Wf2   = (const float*)d_in[6];
    const float* bf2   = (const float*)d_in[7];
    const float* Wg1   = (const float*)d_in[8];
    const float* bg1   = (const float*)d_in[9];
    const float* Wg2   = (const float*)d_in[10];
    const float* bg2   = (const float*)d_in[11];
    float* out = (float*)d_out;

    sde_kernel<<<B_ / 16, 256>>>(a_in, x0, noise,
                                 Wf1, bf1, Wf2, bf2,
                                 Wg1, bg1, Wg2, bg2,
                                 out);
}

// round 17
// speedup vs baseline: 1.4799x; 1.4799x over previous
#include <cuda_runtime.h>

#define B_    2048
#define FS_   32
#define FA_   16
#define T_    512
#define H_    64
#define SQRT_DT_ 0.22360679774997896f
#define MIN_V_  (-5.0f)
#define MAX_V_  (5.0f)

typedef unsigned long long u64;

__device__ __forceinline__ u64 pack2(float lo, float hi) {
    u64 r; asm("mov.b64 %0, {%1, %2};" : "=l"(r) : "f"(lo), "f"(hi)); return r;
}
__device__ __forceinline__ float2 unpack2(u64 v) {
    float2 f; asm("mov.b64 {%0, %1}, %2;" : "=f"(f.x), "=f"(f.y) : "l"(v)); return f;
}
__device__ __forceinline__ u64 ffma2(u64 a, u64 b, u64 c) {
    u64 d; asm("fma.rn.f32x2 %0, %1, %2, %3;" : "=l"(d) : "l"(a), "l"(b), "l"(c)); return d;
}
__device__ __forceinline__ u64 fadd2(u64 a, u64 b) {
    u64 d; asm("add.rn.f32x2 %0, %1, %2;" : "=l"(d) : "l"(a), "l"(b)); return d;
}
// accurate tanh from ex2.approx + rcp.approx (~1e-7 abs err)
__device__ __forceinline__ float tanh_acc(float x) {
    float e, r;
    asm("ex2.approx.f32 %0, %1;" : "=f"(e) : "f"(x * 2.8853900817779268f));
    asm("rcp.approx.f32 %0, %1;" : "=f"(r) : "f"(e + 1.0f));
    return (e - 1.0f) * r;
}

// R10 dataflow (f,g warp pair, full register weights, ONE named barrier/step,
// redundant finalize, q-outer/e-inner loads, batched STG.64), load-balanced
// over ALL 148 SMs: grid=148; blocks carry 14 (x124) or 13 (x24) elements;
// pairs carry E in {3,4} via two template instantiations. All synchronization
// is pair-local named barriers, so per-pair code paths may differ freely.

template<int E>
__device__ __forceinline__ void run_pair(
    const int lane, const bool is_g, const int bar_id, const int gb0,
    const float* __restrict__ x0,
    const float* __restrict__ a_base,
    const float* __restrict__ nz_base,
    float* __restrict__ out_b,
    const u64* __restrict__ w1a, const u64* __restrict__ w1b,
    const u64* __restrict__ w2p,
    const float bias1a, const float bias1b, const float bias2,
    float* __restrict__ vw,     // this warp: [4][64]   (e*64 + j)
    float* __restrict__ asg,    // this pair: [2][4][4][16]  ((buf*4+e)*64 + sl*16 + i)
    float* __restrict__ exg)    // this pair: [2][2][4][32]  (((tb*2+role)*4+e)*32 + lane)
{
    float2 areg[E];
    float  eps_n[E];
    float2 hist[E];

    // -------- prologue (pair-local only) --------
#pragma unroll
    for (int e = 0; e < E; e++) {
        float xv = x0[(size_t)(gb0 + e) * FS_ + lane];
        vw[e * 64 + lane] = xv;
        if (!is_g) hist[e].x = xv;
    }
    if (is_g) {
#pragma unroll
        for (int e = 0; e < E; e++) {
            float2 v = *reinterpret_cast<const float2*>(a_base + (size_t)e * (FA_*T_));
            asg[e * 64 + ((lane & 1) * 2 + 0) * 16 + (lane >> 1)] = v.x;
            asg[e * 64 + ((lane & 1) * 2 + 1) * 16 + (lane >> 1)] = v.y;
        }
#pragma unroll
        for (int e = 0; e < E; e++)
            areg[e] = *reinterpret_cast<const float2*>(a_base + (size_t)e * (FA_*T_) + 4);
#pragma unroll
        for (int e = 0; e < E; e++) eps_n[e] = nz_base[e * FS_];
    }
    asm volatile("bar.sync %0, 64;" :: "r"(bar_id) : "memory");

#pragma unroll 1
    for (int t = 1; t < T_; t++) {
        const int ai  = t - 1;
        const int tb  = t & 1;
        const int g4  = ai >> 2;
        const int buf = g4 & 1;
        const int sl  = ai & 3;

        // g: es for this step; issue next noise loads early
        float es[E];
        if (is_g) {
#pragma unroll
            for (int e = 0; e < E; e++) es[e] = eps_n[e] * SQRT_DT_;
            if (t < T_ - 1) {
                const float* np = nz_base + (size_t)t * (B_ * FS_);
#pragma unroll
                for (int e = 0; e < E; e++) eps_n[e] = np[e * FS_];
            }
        }

        // ---------------- layer 1 (48 -> 64), q-outer / e-inner ----------------
        u64 aa[E], ab[E];
#pragma unroll
        for (int e = 0; e < E; e++) { aa[e] = 0ull; ab[e] = 0ull; }

        // a-part: 4 q-groups
#pragma unroll
        for (int q = 0; q < 4; q++) {
            ulonglong2 v[E];
#pragma unroll
            for (int e = 0; e < E; e++)
                v[e] = *reinterpret_cast<const ulonglong2*>(&asg[(buf * 4 + e) * 64 + sl * 16 + 4 * q]);
            const u64 wA0 = w1a[2*q], wA1 = w1a[2*q+1];
            const u64 wB0 = w1b[2*q], wB1 = w1b[2*q+1];
#pragma unroll
            for (int e = 0; e < E; e++) {
                aa[e] = ffma2(v[e].x, wA0, aa[e]); aa[e] = ffma2(v[e].y, wA1, aa[e]);
                ab[e] = ffma2(v[e].x, wB0, ab[e]); ab[e] = ffma2(v[e].y, wB1, ab[e]);
            }
        }
        // x-part: 8 q-groups
#pragma unroll
        for (int q = 0; q < 8; q++) {
            ulonglong2 v[E];
#pragma unroll
            for (int e = 0; e < E; e++)
                v[e] = *reinterpret_cast<const ulonglong2*>(&vw[e * 64 + 4 * q]);
            const u64 wA0 = w1a[8+2*q], wA1 = w1a[9+2*q];
            const u64 wB0 = w1b[8+2*q], wB1 = w1b[9+2*q];
#pragma unroll
            for (int e = 0; e < E; e++) {
                aa[e] = ffma2(v[e].x, wA0, aa[e]); aa[e] = ffma2(v[e].y, wA1, aa[e]);
                ab[e] = ffma2(v[e].x, wB0, ab[e]); ab[e] = ffma2(v[e].y, wB1, ab[e]);
            }
        }
        // tanh + stash h (overwrites x in private buffer)
#pragma unroll
        for (int e = 0; e < E; e++) {
            float2 u = unpack2(aa[e]);
            float2 w = unpack2(ab[e]);
            vw[e * 64 + lane]      = tanh_acc(u.x + u.y + bias1a);
            vw[e * 64 + lane + 32] = tanh_acc(w.x + w.y + bias1b);
        }
        __syncwarp();

        // ---------------- layer 2 (64 -> 32), q-outer / e-inner ----------------
        u64 c0[E], c1[E];
#pragma unroll
        for (int e = 0; e < E; e++) { c0[e] = 0ull; c1[e] = 0ull; }
#pragma unroll
        for (int q = 0; q < 16; q++) {
            ulonglong2 v[E];
#pragma unroll
            for (int e = 0; e < E; e++)
                v[e] = *reinterpret_cast<const ulonglong2*>(&vw[e * 64 + 4 * q]);
            const u64 w0 = w2p[2*q], w1x = w2p[2*q+1];
#pragma unroll
            for (int e = 0; e < E; e++) {
                c0[e] = ffma2(v[e].x, w0,  c0[e]);
                c1[e] = ffma2(v[e].y, w1x, c1[e]);
            }
        }
        float o[E];
#pragma unroll
        for (int e = 0; e < E; e++) {
            float2 u = unpack2(fadd2(c0[e], c1[e]));
            o[e] = (u.x + u.y) + bias2;
        }

        // publish: f -> o_f (incl. bias), g -> full diffusion term d
        if (!is_g) {
#pragma unroll
            for (int e = 0; e < E; e++) exg[((tb*2 + 0)*4 + e)*32 + lane] = o[e];
        } else {
#pragma unroll
            for (int e = 0; e < E; e++) exg[((tb*2 + 1)*4 + e)*32 + lane] = o[e] * es[e];
        }

        // g: a-tile staging pre-barrier (fills partner-wait window)
        if (is_g) {
            if (sl == 2 && g4 + 1 < 128) {
#pragma unroll
                for (int e = 0; e < E; e++) {
                    asg[((buf ^ 1)*4 + e)*64 + ((lane & 1)*2 + 0)*16 + (lane >> 1)] = areg[e].x;
                    asg[((buf ^ 1)*4 + e)*64 + ((lane & 1)*2 + 1)*16 + (lane >> 1)] = areg[e].y;
                }
            }
            if (sl == 3 && g4 + 2 < 128) {
                const float* ap = a_base + (size_t)(g4 + 2) * 4;
#pragma unroll
                for (int e = 0; e < E; e++)
                    areg[e] = *reinterpret_cast<const float2*>(ap + (size_t)e * (FA_*T_));
            }
        }

        asm volatile("bar.sync %0, 64;" :: "r"(bar_id) : "memory");

        // redundant finalize; f batches output stores into STG.64
#pragma unroll
        for (int e = 0; e < E; e++) {
            float xv = exg[((tb*2 + 0)*4 + e)*32 + lane] + exg[((tb*2 + 1)*4 + e)*32 + lane];
            xv = fminf(fmaxf(xv, MIN_V_), MAX_V_);
            vw[e * 64 + lane] = xv;
            if (!is_g) {
                if (tb) {
                    hist[e].y = xv;
                    *reinterpret_cast<float2*>(out_b + (size_t)e * (FS_*T_) + (t - 1)) = hist[e];
                } else {
                    hist[e].x = xv;
                }
            }
        }
        __syncwarp();
    }
}

__global__ void __launch_bounds__(256, 1)
sde_kernel(const float* __restrict__ a_in,   // (B, FA, T)
           const float* __restrict__ x0,     // (B, FS)
           const float* __restrict__ noise,  // (T-1, B, FS)
           const float* __restrict__ Wf1, const float* __restrict__ bf1,
           const float* __restrict__ Wf2, const float* __restrict__ bf2,
           const float* __restrict__ Wg1, const float* __restrict__ bg1,
           const float* __restrict__ Wg2, const float* __restrict__ bg2,
           float* __restrict__ out)          // (B, FS, T)
{
    const int tid  = threadIdx.x;
    const int wid  = tid >> 5;
    const int lane = tid & 31;
    const int pair = wid >> 1;            // 0..3
    const bool is_g = (wid & 1) != 0;

    // element mapping: 124 blocks x 14 el + 24 blocks x 13 el = 2048
    const bool typeA = (blockIdx.x < 124);
    const int blkbase = typeA ? (int)blockIdx.x * 14
                              : 1736 + ((int)blockIdx.x - 124) * 13;
    const int pE    = typeA ? ((pair < 2) ? 4 : 3) : ((pair == 0) ? 4 : 3);
    const int pbase = typeA ? ((pair < 3) ? pair * 4 : 11)
                            : ((pair == 0) ? 0 : 3 * pair + 1);
    const int gb0 = blkbase + pbase;

    __shared__ __align__(16) float v_sm[8][4][64];        // per-warp x/h buffer
    __shared__ __align__(16) float a_sg[4][2][4][4][16];  // per-pair a tiles
    __shared__ __align__(16) float ex_sm[4][2][2][4][32]; // per-pair exchange

    const float* W1 = is_g ? Wg1 : Wf1;
    const float* b1 = is_g ? bg1 : bf1;
    const float* W2 = is_g ? Wg2 : Wf2;
    const float* b2 = is_g ? bg2 : bf2;

    u64 w1a[24], w1b[24], w2p[32];
#pragma unroll
    for (int kp = 0; kp < 24; kp++) {
        w1a[kp] = pack2(W1[(2*kp)*H_ + lane],      W1[(2*kp+1)*H_ + lane]);
        w1b[kp] = pack2(W1[(2*kp)*H_ + lane + 32], W1[(2*kp+1)*H_ + lane + 32]);
    }
#pragma unroll
    for (int kp = 0; kp < 32; kp++) {
        w2p[kp] = pack2(W2[(2*kp)*FS_ + lane], W2[(2*kp+1)*FS_ + lane]);
    }
    const float bias1a = b1[lane];
    const float bias1b = b1[lane + 32];
    const float bias2  = b2[lane];

    const float* a_base  = a_in  + (size_t)gb0 * (FA_*T_) + (size_t)(lane >> 1) * T_ + (lane & 1) * 2;
    const float* nz_base = noise + (size_t)gb0 * FS_ + lane;
    float*       out_b   = out   + (size_t)gb0 * (FS_*T_) + (size_t)lane * T_;

    float* vw  = &v_sm[wid][0][0];
    float* asg = &a_sg[pair][0][0][0][0];
    float* exg = &ex_sm[pair][0][0][0][0];
    const int bar_id = 1 + pair;

    if (pE == 4) {
        run_pair<4>(lane, is_g, bar_id, gb0, x0, a_base, nz_base, out_b,
                    w1a, w1b, w2p, bias1a, bias1b, bias2, vw, asg, exg);
    } else {
        run_pair<3>(lane, is_g, bar_id, gb0, x0, a_base, nz_base, out_b,
                    w1a, w1b, w2p, bias1a, bias1b, bias2, vw, asg, exg);
    }
}

extern "C" void kernel_launch(void* const* d_in, const int* in_sizes, int n_in,
                              void* d_out, int out_size) {
    (void)in_sizes; (void)n_in; (void)out_size;
    // metadata order: ts, in_signal, x0, noise, Wf1, bf1, Wf2, bf2, Wg1, bg1, Wg2, bg2
    const float* a_in  = (const float*)d_in[1];
    const float* x0    = (const float*)d_in[2];
    const float* noise = (const float*)d_in[3];
    const float* Wf1   = (const float*)d_in[4];
    const float* bf1   = (const float*)d_in[5];
    const float* Wf2   = (const float*)d_in[6];
    const float* bf2   = (const float*)d_in[7];
    const float* Wg1   = (const float*)d_in[8];
    const float* bg1   = (const float*)d_in[9];
    const float* Wg2   = (const float*)d_in[10];
    const float* bg2   = (const float*)d_in[11];
    float* out = (float*)d_out;

    sde_kernel<<<148, 256>>>(a_in, x0, noise,
                             Wf1, bf1, Wf2, bf2,
                             Wg1, bg1, Wg2, bg2,
                             out);
}